// round 10
// baseline (speedup 1.0000x reference)
#include <cuda_runtime.h>
#include <math.h>

#define HH 512
#define WW 512
#define BB 32
#define CCH 3
#define NK 6
#define NCHUNK 16
#define CROWS 32          // HH / NCHUNK
#define R3ROWS 8
#define TWO_PI 6.283185307179586f

typedef unsigned long long u64;

__device__ __forceinline__ u64 pk(float lo, float hi) {
    u64 r; asm("mov.b64 %0,{%1,%2};" : "=l"(r) : "f"(lo), "f"(hi)); return r;
}
__device__ __forceinline__ float2 upk(u64 v) {
    float2 f; asm("mov.b64 {%0,%1},%2;" : "=f"(f.x), "=f"(f.y) : "l"(v)); return f;
}
__device__ __forceinline__ u64 fma2_(u64 a, u64 b, u64 c) {
    u64 d; asm("fma.rn.f32x2 %0,%1,%2,%3;" : "=l"(d) : "l"(a), "l"(b), "l"(c)); return d;
}
__device__ __forceinline__ u64 mul2_(u64 a, u64 b) {
    u64 d; asm("mul.rn.f32x2 %0,%1,%2;" : "=l"(d) : "l"(a), "l"(b)); return d;
}
__device__ __forceinline__ u64 add2_(u64 a, u64 b) {
    u64 d; asm("add.rn.f32x2 %0,%1,%2;" : "=l"(d) : "l"(a), "l"(b)); return d;
}
__device__ __forceinline__ u64 neg2_(u64 a) { return a ^ 0x8000000080000000ULL; }

// Scratch (device globals — no allocation allowed)
__device__ float g_Fpart[BB * CCH * NCHUNK * 72];  // [bc][chunk][u*6+k][re,im]
__device__ float g_gg[BB * CCH * HH * NK * 2];     // [bc][h][k][re,im]

// ---------------------------------------------------------------------------
// Kernel 1: partial F[u][k] over a 32-row tile. Real-input symmetry:
// only 7 accumulators (S0, Cr1..3, Ci1..3) and 3 complex twiddles per row.
// Thread = float4 of w. Block 128, grid (16, 96) = 1536 blocks.
// ---------------------------------------------------------------------------
__global__ __launch_bounds__(128) void k1_coldft(const float* __restrict__ x) {
    const int chunk = blockIdx.x;
    const int bc    = blockIdx.y;
    const int t     = threadIdx.x;
    const int h0    = chunk * CROWS;

    __shared__ __align__(16) u64 twc[CROWS][3], tws[CROWS][3]; // (c,c) / (s,s) for K=1..3
    __shared__ float sm_part[4][72];

    for (int i = t; i < CROWS * 3; i += 128) {
        int hl = i / 3, K = (i % 3) + 1;
        float a = TWO_PI * (float)(h0 + hl) * (1.0f / (float)HH) * (float)K;
        float s, c; __sincosf(a, &s, &c);
        twc[hl][K - 1] = pk(c, c);
        tws[hl][K - 1] = pk(s, s);
    }
    __syncthreads();

    u64 S0[2] = {0ULL, 0ULL};
    u64 Cr[3][2], Ci[3][2];
#pragma unroll
    for (int K = 0; K < 3; K++) { Cr[K][0] = Cr[K][1] = 0ULL; Ci[K][0] = Ci[K][1] = 0ULL; }

    const float4* xp = (const float4*)(x + (size_t)bc * HH * WW + (size_t)h0 * WW) + t;
#pragma unroll 8
    for (int hl = 0; hl < CROWS; ++hl) {
        float4 v = __ldg(xp + (size_t)hl * (WW / 4));
        u64 v01 = pk(v.x, v.y), v23 = pk(v.z, v.w);
        S0[0] = add2_(S0[0], v01);
        S0[1] = add2_(S0[1], v23);
#pragma unroll
        for (int K = 0; K < 3; K++) {
            u64 cc = twc[hl][K], ss = tws[hl][K];
            Cr[K][0] = fma2_(v01, cc, Cr[K][0]);
            Ci[K][0] = fma2_(v01, ss, Ci[K][0]);
            Cr[K][1] = fma2_(v23, cc, Cr[K][1]);
            Ci[K][1] = fma2_(v23, ss, Ci[K][1]);
        }
    }

    // reconstruct full column sums:
    //   u = 3-K -> (Cr, +Ci) ; u = 3+K -> (Cr, -Ci) ; u = 3 -> (S0, 0)
    float cre[6][4], cim[6][4];
    {
        float2 a0 = upk(S0[0]), a1 = upk(S0[1]);
        cre[3][0] = a0.x; cre[3][1] = a0.y; cre[3][2] = a1.x; cre[3][3] = a1.y;
        cim[3][0] = cim[3][1] = cim[3][2] = cim[3][3] = 0.f;
#pragma unroll
        for (int K = 1; K <= 3; K++) {
            float2 r0 = upk(Cr[K - 1][0]), r1 = upk(Cr[K - 1][1]);
            float2 i0 = upk(Ci[K - 1][0]), i1 = upk(Ci[K - 1][1]);
            float rv[4] = { r0.x, r0.y, r1.x, r1.y };
            float iv[4] = { i0.x, i0.y, i1.x, i1.y };
            int um = 3 - K, up = 3 + K;
#pragma unroll
            for (int j = 0; j < 4; j++) {
                cre[um][j] = rv[j]; cim[um][j] = iv[j];
                if (up < 6) { cre[up][j] = rv[j]; cim[up][j] = -iv[j]; }
            }
        }
    }

    // E_k[w] = e^{-i (k-3) phi_w} for this thread's 4 w's
    float Ec[4][6], Es[4][6];
#pragma unroll
    for (int j = 0; j < 4; j++) {
        float phi = TWO_PI * (float)(4 * t + j) * (1.0f / (float)WW);
        float c1, s1; __sincosf(phi, &s1, &c1);
        float c2 = c1 * c1 - s1 * s1, s2 = 2.f * c1 * s1;
        float c3 = c2 * c1 - s2 * s1, s3 = c2 * s1 + s2 * c1;
        Ec[j][0] = c3; Es[j][0] = s3;
        Ec[j][1] = c2; Es[j][1] = s2;
        Ec[j][2] = c1; Es[j][2] = s1;
        Ec[j][3] = 1.f; Es[j][3] = 0.f;
        Ec[j][4] = c1; Es[j][4] = -s1;
        Ec[j][5] = c2; Es[j][5] = -s2;
    }

    const int wid = t >> 5, lid = t & 31;
#pragma unroll
    for (int u = 0; u < 6; u++) {
        float fr[6], fi[6];
#pragma unroll
        for (int k = 0; k < 6; k++) { fr[k] = 0.f; fi[k] = 0.f; }
#pragma unroll
        for (int j = 0; j < 4; j++) {
            float gr = cre[u][j], gi = cim[u][j];
#pragma unroll
            for (int k = 0; k < 6; k++) {
                fr[k] = fmaf(gr, Ec[j][k], fmaf(-gi, Es[j][k], fr[k]));
                fi[k] = fmaf(gr, Es[j][k], fmaf( gi, Ec[j][k], fi[k]));
            }
        }
#pragma unroll
        for (int off = 16; off >= 1; off >>= 1) {
#pragma unroll
            for (int k = 0; k < 6; k++) {
                fr[k] += __shfl_xor_sync(0xFFFFFFFFu, fr[k], off);
                fi[k] += __shfl_xor_sync(0xFFFFFFFFu, fi[k], off);
            }
        }
        if (lid == 0) {
#pragma unroll
            for (int k = 0; k < 6; k++) {
                sm_part[wid][(u * 6 + k) * 2 + 0] = fr[k];
                sm_part[wid][(u * 6 + k) * 2 + 1] = fi[k];
            }
        }
    }
    __syncthreads();

    if (t < 72) {
        float s = sm_part[0][t] + sm_part[1][t] + sm_part[2][t] + sm_part[3][t];
        g_Fpart[((size_t)bc * NCHUNK + chunk) * 72 + t] = s;
    }
}

// ---------------------------------------------------------------------------
// Kernel 2: per (b,c): sum chunk partials -> F (normalized), then
// g_gg[h][k] = sum_u F[u][k] e^{+2pi i (u-3) h/512}.  grid 96, block 512.
// ---------------------------------------------------------------------------
__global__ __launch_bounds__(512) void k2_reduce() {
    const int bc = blockIdx.x;
    const int t  = threadIdx.x;

    __shared__ float F[72];

    if (t < 72) {
        const float* fp = g_Fpart + (size_t)bc * NCHUNK * 72 + t;
        float s = 0.f;
#pragma unroll
        for (int c = 0; c < NCHUNK; c++) s += fp[c * 72];
        F[t] = s * (1.0f / ((float)HH * (float)WW));
    }
    __syncthreads();

    {
        float psi = TWO_PI * (float)t * (1.0f / (float)HH);
        float d1c, d1s; __sincosf(psi, &d1s, &d1c);
        float d2c = d1c * d1c - d1s * d1s, d2s = 2.f * d1c * d1s;
        float d3c = d2c * d1c - d2s * d1s, d3s = d2c * d1s + d2s * d1c;
        float Dc[6] = { d3c,  d2c,  d1c,  1.f, d1c, d2c };
        float Ds[6] = { -d3s, -d2s, -d1s, 0.f, d1s, d2s };

        float* ggp = g_gg + (((size_t)bc * HH + t) * NK) * 2;
#pragma unroll
        for (int k = 0; k < 6; k++) {
            float gr = 0.f, gi = 0.f;
#pragma unroll
            for (int u = 0; u < 6; u++) {
                float Fr = F[(u * 6 + k) * 2 + 0];
                float Fi = F[(u * 6 + k) * 2 + 1];
                gr += Fr * Dc[u] - Fi * Ds[u];
                gi += Fr * Ds[u] + Fi * Dc[u];
            }
            ggp[k * 2 + 0] = gr;
            ggp[k * 2 + 1] = gi;
        }
    }
}

// ---------------------------------------------------------------------------
// Kernel 3: reconstruction + MLP + residual + clip, fully packed f32x2.
// Thread = 2 adjacent pixels. Weights pre-packed (w,w) in registers.
// Recon uses 4 independent accumulators per channel (no packed negates in loop).
// grid (H/8, B) = (64, 32), block 256.
// ---------------------------------------------------------------------------
__global__ __launch_bounds__(256) void k3_final(const float* __restrict__ w1,
                                                const float* __restrict__ b1,
                                                const float* __restrict__ w2,
                                                const float* __restrict__ b2,
                                                float* __restrict__ out) {
    const int b  = blockIdx.y;
    const int h0 = blockIdx.x * R3ROWS;
    const int t  = threadIdx.x;   // pixel pair (2t, 2t+1)

    __shared__ __align__(16) u64 sg2[R3ROWS * 36];  // (v,v) pairs: [(r*3+ch)*12 + k*2 + {re,im}]
    __shared__ float wt[64];

    for (int i = t; i < R3ROWS * 36; i += 256) {
        int r  = i / 36;
        int ch = (i % 36) / 12;
        int j  = i % 12;
        float v = g_gg[(((size_t)(b * 3 + ch) * HH) + (h0 + r)) * 12 + j];
        sg2[i] = pk(v, v);
    }
    if (t < 24)      wt[t] = w1[t];
    else if (t < 32) wt[t] = b1[t - 24];
    else if (t < 56) wt[t] = w2[t - 32];
    else if (t < 59) wt[t] = b2[t - 56];
    __syncthreads();

    // packed (w,w) weights in registers
    u64 W1p[8][3], B1p[8], W2p[3][8], B2p[3];
#pragma unroll
    for (int j = 0; j < 8; j++) {
#pragma unroll
        for (int cc = 0; cc < 3; cc++) { float v = wt[j * 3 + cc]; W1p[j][cc] = pk(v, v); }
        { float v = wt[24 + j]; B1p[j] = pk(v, v); }
    }
#pragma unroll
    for (int cc = 0; cc < 3; cc++) {
#pragma unroll
        for (int j = 0; j < 8; j++) { float v = wt[32 + cc * 8 + j]; W2p[cc][j] = pk(v, v); }
        { float v = wt[56 + cc]; B2p[cc] = pk(v, v); }
    }

    // E^k for k=1..5, packed for the 2 pixels
    u64 Ec[6], Es[6];
    {
        const int w0 = 2 * t;
        float cA, sA, cB, sB;
        __sincosf(TWO_PI * (float)w0       * (1.0f / (float)WW), &sA, &cA);
        __sincosf(TWO_PI * (float)(w0 + 1) * (1.0f / (float)WW), &sB, &cB);
        u64 e1c = pk(cA, cB), e1s = pk(sA, sB);
        Ec[1] = e1c; Es[1] = e1s;
#pragma unroll
        for (int k = 2; k <= 5; k++) {
            Ec[k] = fma2_(Ec[k - 1], e1c, neg2_(mul2_(Es[k - 1], e1s)));
            Es[k] = fma2_(Ec[k - 1], e1s, mul2_(Es[k - 1], e1c));
        }
    }

#pragma unroll
    for (int r = 0; r < R3ROWS; ++r) {
        u64 lp2[3];
#pragma unroll
        for (int ch = 0; ch < 3; ch++) {
            const ulonglong2* g = (const ulonglong2*)&sg2[(r * 3 + ch) * 12];
            ulonglong2 g0 = g[0];
            // 4 independent accumulator chains: zr = zr1 - zr2, zi = zi1 + zi2
            u64 zr1 = g0.x, zr2 = 0ULL, zi1 = 0ULL, zi2 = g0.y;
#pragma unroll
            for (int k = 1; k <= 5; ++k) {
                ulonglong2 gk = g[k];          // LDS.128 broadcast (re, im)
                zr1 = fma2_(gk.x, Ec[k], zr1);
                zr2 = fma2_(gk.y, Es[k], zr2);
                zi1 = fma2_(gk.x, Es[k], zi1);
                zi2 = fma2_(gk.y, Ec[k], zi2);
            }
            u64 zr = add2_(zr1, neg2_(zr2));
            u64 zi = add2_(zi1, zi2);
            u64 m2 = fma2_(zr, zr, mul2_(zi, zi));
            float2 m = upk(m2);
            float m0 = fmaxf(m.x, 1e-30f), m1 = fmaxf(m.y, 1e-30f);
            lp2[ch] = pk(m0 * __frsqrt_rn(m0), m1 * __frsqrt_rn(m1));
        }

        // hidden layer packed; relu via brief scalar unpack (ALU pipe)
        u64 h2[8];
#pragma unroll
        for (int j = 0; j < 8; j++) {
            u64 a = fma2_(W1p[j][2], lp2[2],
                     fma2_(W1p[j][1], lp2[1],
                      fma2_(W1p[j][0], lp2[0], B1p[j])));
            float2 hv = upk(a);
            h2[j] = pk(fmaxf(hv.x, 0.f), fmaxf(hv.y, 0.f));
        }

#pragma unroll
        for (int ch = 0; ch < 3; ch++) {
            u64 y2 = add2_(lp2[ch], B2p[ch]);
#pragma unroll
            for (int j = 0; j < 8; j++) y2 = fma2_(W2p[ch][j], h2[j], y2);
            float2 yv = upk(y2);
            float2 yo = make_float2(__saturatef(yv.x), __saturatef(yv.y));
            float2* orow = (float2*)(out + (((size_t)(b * 3 + ch) * HH) + (h0 + r)) * WW);
            orow[t] = yo;
        }
    }
}

// ---------------------------------------------------------------------------
extern "C" void kernel_launch(void* const* d_in, const int* in_sizes, int n_in,
                              void* d_out, int out_size) {
    const float* x  = (const float*)d_in[0];
    const float* w1 = (const float*)d_in[1];
    const float* b1 = (const float*)d_in[2];
    const float* w2 = (const float*)d_in[3];
    const float* b2 = (const float*)d_in[4];
    float* out = (float*)d_out;

    k1_coldft<<<dim3(NCHUNK, BB * CCH), 128>>>(x);
    k2_reduce<<<BB * CCH, 512>>>();
    k3_final<<<dim3(HH / R3ROWS, BB), 256>>>(w1, b1, w2, b2, out);
}

// round 11
// speedup vs baseline: 1.0110x; 1.0110x over previous
#include <cuda_runtime.h>
#include <math.h>

#define HH 512
#define WW 512
#define BB 32
#define CCH 3
#define NK 6
#define NCHUNK 8
#define CROWS 64          // HH / NCHUNK
#define R3ROWS 8
#define TWO_PI 6.283185307179586f

typedef unsigned long long u64;

__device__ __forceinline__ u64 pk(float lo, float hi) {
    u64 r; asm("mov.b64 %0,{%1,%2};" : "=l"(r) : "f"(lo), "f"(hi)); return r;
}
__device__ __forceinline__ float2 upk(u64 v) {
    float2 f; asm("mov.b64 {%0,%1},%2;" : "=f"(f.x), "=f"(f.y) : "l"(v)); return f;
}
__device__ __forceinline__ u64 fma2_(u64 a, u64 b, u64 c) {
    u64 d; asm("fma.rn.f32x2 %0,%1,%2,%3;" : "=l"(d) : "l"(a), "l"(b), "l"(c)); return d;
}
__device__ __forceinline__ u64 mul2_(u64 a, u64 b) {
    u64 d; asm("mul.rn.f32x2 %0,%1,%2;" : "=l"(d) : "l"(a), "l"(b)); return d;
}
__device__ __forceinline__ u64 add2_(u64 a, u64 b) {
    u64 d; asm("add.rn.f32x2 %0,%1,%2;" : "=l"(d) : "l"(a), "l"(b)); return d;
}
__device__ __forceinline__ u64 neg2_(u64 a) { return a ^ 0x8000000080000000ULL; }

// Scratch (device globals — no allocation allowed)
__device__ float g_Fpart[BB * CCH * NCHUNK * 72];  // [bc][chunk][u*6+k][re,im]
__device__ float g_gg[BB * CCH * HH * NK * 2];     // [bc][h][k][re,im]

// ---------------------------------------------------------------------------
// Kernel 1 (identical to R9 measured 27.3us): partial F[u][k] over 64-row tile.
// Real-input symmetry: 7 accumulators, 3 complex twiddles per row.
// Thread = float4 of w. Block 128, grid (8, 96) = 768 blocks.
// ---------------------------------------------------------------------------
__global__ __launch_bounds__(128) void k1_coldft(const float* __restrict__ x) {
    const int chunk = blockIdx.x;
    const int bc    = blockIdx.y;
    const int t     = threadIdx.x;
    const int h0    = chunk * CROWS;

    __shared__ __align__(16) u64 twc[CROWS][3], tws[CROWS][3];
    __shared__ float sm_part[4][72];

    for (int i = t; i < CROWS * 3; i += 128) {
        int hl = i / 3, K = (i % 3) + 1;
        float a = TWO_PI * (float)(h0 + hl) * (1.0f / (float)HH) * (float)K;
        float s, c; __sincosf(a, &s, &c);
        twc[hl][K - 1] = pk(c, c);
        tws[hl][K - 1] = pk(s, s);
    }
    __syncthreads();

    u64 S0[2] = {0ULL, 0ULL};
    u64 Cr[3][2], Ci[3][2];
#pragma unroll
    for (int K = 0; K < 3; K++) { Cr[K][0] = Cr[K][1] = 0ULL; Ci[K][0] = Ci[K][1] = 0ULL; }

    const float4* xp = (const float4*)(x + (size_t)bc * HH * WW + (size_t)h0 * WW) + t;
#pragma unroll 8
    for (int hl = 0; hl < CROWS; ++hl) {
        float4 v = __ldg(xp + (size_t)hl * (WW / 4));
        u64 v01 = pk(v.x, v.y), v23 = pk(v.z, v.w);
        S0[0] = add2_(S0[0], v01);
        S0[1] = add2_(S0[1], v23);
#pragma unroll
        for (int K = 0; K < 3; K++) {
            u64 cc = twc[hl][K], ss = tws[hl][K];
            Cr[K][0] = fma2_(v01, cc, Cr[K][0]);
            Ci[K][0] = fma2_(v01, ss, Ci[K][0]);
            Cr[K][1] = fma2_(v23, cc, Cr[K][1]);
            Ci[K][1] = fma2_(v23, ss, Ci[K][1]);
        }
    }

    float cre[6][4], cim[6][4];
    {
        float2 a0 = upk(S0[0]), a1 = upk(S0[1]);
        cre[3][0] = a0.x; cre[3][1] = a0.y; cre[3][2] = a1.x; cre[3][3] = a1.y;
        cim[3][0] = cim[3][1] = cim[3][2] = cim[3][3] = 0.f;
#pragma unroll
        for (int K = 1; K <= 3; K++) {
            float2 r0 = upk(Cr[K - 1][0]), r1 = upk(Cr[K - 1][1]);
            float2 i0 = upk(Ci[K - 1][0]), i1 = upk(Ci[K - 1][1]);
            float rv[4] = { r0.x, r0.y, r1.x, r1.y };
            float iv[4] = { i0.x, i0.y, i1.x, i1.y };
            int um = 3 - K, up = 3 + K;
#pragma unroll
            for (int j = 0; j < 4; j++) {
                cre[um][j] = rv[j]; cim[um][j] = iv[j];
                if (up < 6) { cre[up][j] = rv[j]; cim[up][j] = -iv[j]; }
            }
        }
    }

    float Ec[4][6], Es[4][6];
#pragma unroll
    for (int j = 0; j < 4; j++) {
        float phi = TWO_PI * (float)(4 * t + j) * (1.0f / (float)WW);
        float c1, s1; __sincosf(phi, &s1, &c1);
        float c2 = c1 * c1 - s1 * s1, s2 = 2.f * c1 * s1;
        float c3 = c2 * c1 - s2 * s1, s3 = c2 * s1 + s2 * c1;
        Ec[j][0] = c3; Es[j][0] = s3;
        Ec[j][1] = c2; Es[j][1] = s2;
        Ec[j][2] = c1; Es[j][2] = s1;
        Ec[j][3] = 1.f; Es[j][3] = 0.f;
        Ec[j][4] = c1; Es[j][4] = -s1;
        Ec[j][5] = c2; Es[j][5] = -s2;
    }

    const int wid = t >> 5, lid = t & 31;
#pragma unroll
    for (int u = 0; u < 6; u++) {
        float fr[6], fi[6];
#pragma unroll
        for (int k = 0; k < 6; k++) { fr[k] = 0.f; fi[k] = 0.f; }
#pragma unroll
        for (int j = 0; j < 4; j++) {
            float gr = cre[u][j], gi = cim[u][j];
#pragma unroll
            for (int k = 0; k < 6; k++) {
                fr[k] = fmaf(gr, Ec[j][k], fmaf(-gi, Es[j][k], fr[k]));
                fi[k] = fmaf(gr, Es[j][k], fmaf( gi, Ec[j][k], fi[k]));
            }
        }
#pragma unroll
        for (int off = 16; off >= 1; off >>= 1) {
#pragma unroll
            for (int k = 0; k < 6; k++) {
                fr[k] += __shfl_xor_sync(0xFFFFFFFFu, fr[k], off);
                fi[k] += __shfl_xor_sync(0xFFFFFFFFu, fi[k], off);
            }
        }
        if (lid == 0) {
#pragma unroll
            for (int k = 0; k < 6; k++) {
                sm_part[wid][(u * 6 + k) * 2 + 0] = fr[k];
                sm_part[wid][(u * 6 + k) * 2 + 1] = fi[k];
            }
        }
    }
    __syncthreads();

    if (t < 72) {
        float s = sm_part[0][t] + sm_part[1][t] + sm_part[2][t] + sm_part[3][t];
        g_Fpart[((size_t)bc * NCHUNK + chunk) * 72 + t] = s;
    }
}

// ---------------------------------------------------------------------------
// Kernel 2: per (b,c): sum chunk partials -> F (normalized), then
// g_gg[h][k] = sum_u F[u][k] e^{+2pi i (u-3) h/512}.  grid 96, block 512.
// ---------------------------------------------------------------------------
__global__ __launch_bounds__(512) void k2_reduce() {
    const int bc = blockIdx.x;
    const int t  = threadIdx.x;

    __shared__ float F[72];

    if (t < 72) {
        const float* fp = g_Fpart + (size_t)bc * NCHUNK * 72 + t;
        float s = 0.f;
#pragma unroll
        for (int c = 0; c < NCHUNK; c++) s += fp[c * 72];
        F[t] = s * (1.0f / ((float)HH * (float)WW));
    }
    __syncthreads();

    {
        float psi = TWO_PI * (float)t * (1.0f / (float)HH);
        float d1c, d1s; __sincosf(psi, &d1s, &d1c);
        float d2c = d1c * d1c - d1s * d1s, d2s = 2.f * d1c * d1s;
        float d3c = d2c * d1c - d2s * d1s, d3s = d2c * d1s + d2s * d1c;
        float Dc[6] = { d3c,  d2c,  d1c,  1.f, d1c, d2c };
        float Ds[6] = { -d3s, -d2s, -d1s, 0.f, d1s, d2s };

        float* ggp = g_gg + (((size_t)bc * HH + t) * NK) * 2;
#pragma unroll
        for (int k = 0; k < 6; k++) {
            float gr = 0.f, gi = 0.f;
#pragma unroll
            for (int u = 0; u < 6; u++) {
                float Fr = F[(u * 6 + k) * 2 + 0];
                float Fi = F[(u * 6 + k) * 2 + 1];
                gr += Fr * Dc[u] - Fi * Ds[u];
                gi += Fr * Ds[u] + Fi * Dc[u];
            }
            ggp[k * 2 + 0] = gr;
            ggp[k * 2 + 1] = gi;
        }
    }
}

// ---------------------------------------------------------------------------
// Kernel 3: packed recon + packed MLP with PAIRED HIDDEN UNITS:
// W1/W2 pack two different hidden units per u64 against broadcast (lp,lp),
// halving weight register cost vs R10 (48 regs vs 118). Output layer sums
// the two lanes at the end; b2 + lp residual folded into lane 0 of the init.
// Thread = 2 adjacent pixels. grid (H/8, B) = (64, 32), block 256.
// ---------------------------------------------------------------------------
__global__ __launch_bounds__(256) void k3_final(const float* __restrict__ w1,
                                                const float* __restrict__ b1,
                                                const float* __restrict__ w2,
                                                const float* __restrict__ b2,
                                                float* __restrict__ out) {
    const int b  = blockIdx.y;
    const int h0 = blockIdx.x * R3ROWS;
    const int t  = threadIdx.x;   // pixel pair (2t, 2t+1)

    __shared__ __align__(16) u64 sg2[R3ROWS * 36];  // (v,v) pairs
    __shared__ float wt[64];

    for (int i = t; i < R3ROWS * 36; i += 256) {
        int r  = i / 36;
        int ch = (i % 36) / 12;
        int j  = i % 12;
        float v = g_gg[(((size_t)(b * 3 + ch) * HH) + (h0 + r)) * 12 + j];
        sg2[i] = pk(v, v);
    }
    if (t < 24)      wt[t] = w1[t];
    else if (t < 32) wt[t] = b1[t - 24];
    else if (t < 56) wt[t] = w2[t - 32];
    else if (t < 59) wt[t] = b2[t - 56];
    __syncthreads();

    // paired-unit packed weights: lane0 = unit 2jp, lane1 = unit 2jp+1
    u64 W1p[4][3], B1p[4], W2p[3][4];
    float B2s[3];
#pragma unroll
    for (int jp = 0; jp < 4; jp++) {
#pragma unroll
        for (int cc = 0; cc < 3; cc++)
            W1p[jp][cc] = pk(wt[(2 * jp) * 3 + cc], wt[(2 * jp + 1) * 3 + cc]);
        B1p[jp] = pk(wt[24 + 2 * jp], wt[24 + 2 * jp + 1]);
    }
#pragma unroll
    for (int cc = 0; cc < 3; cc++) {
#pragma unroll
        for (int jp = 0; jp < 4; jp++)
            W2p[cc][jp] = pk(wt[32 + cc * 8 + 2 * jp], wt[32 + cc * 8 + 2 * jp + 1]);
        B2s[cc] = wt[56 + cc];
    }

    // E^k for k=1..5, packed for the 2 pixels
    u64 Ec[6], Es[6];
    {
        const int w0 = 2 * t;
        float cA, sA, cB, sB;
        __sincosf(TWO_PI * (float)w0       * (1.0f / (float)WW), &sA, &cA);
        __sincosf(TWO_PI * (float)(w0 + 1) * (1.0f / (float)WW), &sB, &cB);
        u64 e1c = pk(cA, cB), e1s = pk(sA, sB);
        Ec[1] = e1c; Es[1] = e1s;
#pragma unroll
        for (int k = 2; k <= 5; k++) {
            Ec[k] = fma2_(Ec[k - 1], e1c, neg2_(mul2_(Es[k - 1], e1s)));
            Es[k] = fma2_(Ec[k - 1], e1s, mul2_(Es[k - 1], e1c));
        }
    }

#pragma unroll
    for (int r = 0; r < R3ROWS; ++r) {
        float lpA[3], lpB[3];
#pragma unroll
        for (int ch = 0; ch < 3; ch++) {
            const ulonglong2* g = (const ulonglong2*)&sg2[(r * 3 + ch) * 12];
            ulonglong2 g0 = g[0];
            u64 zr1 = g0.x, zr2 = 0ULL, zi1 = 0ULL, zi2 = g0.y;
#pragma unroll
            for (int k = 1; k <= 5; ++k) {
                ulonglong2 gk = g[k];          // LDS.128 broadcast (re, im)
                zr1 = fma2_(gk.x, Ec[k], zr1);
                zr2 = fma2_(gk.y, Es[k], zr2);
                zi1 = fma2_(gk.x, Es[k], zi1);
                zi2 = fma2_(gk.y, Ec[k], zi2);
            }
            u64 zr = add2_(zr1, neg2_(zr2));
            u64 zi = add2_(zi1, zi2);
            u64 m2 = fma2_(zr, zr, mul2_(zi, zi));
            float2 m = upk(m2);
            float m0 = fmaxf(m.x, 1e-30f), m1 = fmaxf(m.y, 1e-30f);
            lpA[ch] = m0 * __frsqrt_rn(m0);
            lpB[ch] = m1 * __frsqrt_rn(m1);
        }

        // broadcast lp per pixel for paired-unit MLP
        u64 lA0 = pk(lpA[0], lpA[0]), lA1 = pk(lpA[1], lpA[1]), lA2 = pk(lpA[2], lpA[2]);
        u64 lB0 = pk(lpB[0], lpB[0]), lB1 = pk(lpB[1], lpB[1]), lB2 = pk(lpB[2], lpB[2]);

        u64 hA[4], hB[4];
#pragma unroll
        for (int jp = 0; jp < 4; jp++) {
            u64 aA = fma2_(W1p[jp][2], lA2, fma2_(W1p[jp][1], lA1, fma2_(W1p[jp][0], lA0, B1p[jp])));
            u64 aB = fma2_(W1p[jp][2], lB2, fma2_(W1p[jp][1], lB1, fma2_(W1p[jp][0], lB0, B1p[jp])));
            float2 vA = upk(aA), vB = upk(aB);
            hA[jp] = pk(fmaxf(vA.x, 0.f), fmaxf(vA.y, 0.f));
            hB[jp] = pk(fmaxf(vB.x, 0.f), fmaxf(vB.y, 0.f));
        }

#pragma unroll
        for (int ch = 0; ch < 3; ch++) {
            // fold b2 + lp residual into lane 0 of the init
            u64 accA = pk(B2s[ch] + lpA[ch], 0.f);
            u64 accB = pk(B2s[ch] + lpB[ch], 0.f);
#pragma unroll
            for (int jp = 0; jp < 4; jp++) {
                accA = fma2_(W2p[ch][jp], hA[jp], accA);
                accB = fma2_(W2p[ch][jp], hB[jp], accB);
            }
            float2 vA = upk(accA), vB = upk(accB);
            float2 yo = make_float2(__saturatef(vA.x + vA.y), __saturatef(vB.x + vB.y));
            float2* orow = (float2*)(out + (((size_t)(b * 3 + ch) * HH) + (h0 + r)) * WW);
            orow[t] = yo;
        }
    }
}

// ---------------------------------------------------------------------------
extern "C" void kernel_launch(void* const* d_in, const int* in_sizes, int n_in,
                              void* d_out, int out_size) {
    const float* x  = (const float*)d_in[0];
    const float* w1 = (const float*)d_in[1];
    const float* b1 = (const float*)d_in[2];
    const float* w2 = (const float*)d_in[3];
    const float* b2 = (const float*)d_in[4];
    float* out = (float*)d_out;

    k1_coldft<<<dim3(NCHUNK, BB * CCH), 128>>>(x);
    k2_reduce<<<BB * CCH, 512>>>();
    k3_final<<<dim3(HH / R3ROWS, BB), 256>>>(w1, b1, w2, b2, out);
}

// round 12
// speedup vs baseline: 1.0879x; 1.0760x over previous
#include <cuda_runtime.h>
#include <math.h>

#define HH 512
#define WW 512
#define BB 32
#define CCH 3
#define NK 6
#define NCHUNK 8
#define CROWS 64          // HH / NCHUNK
#define R3ROWS 8
#define TWO_PI 6.283185307179586f

typedef unsigned long long u64;

__device__ __forceinline__ u64 pk(float lo, float hi) {
    u64 r; asm("mov.b64 %0,{%1,%2};" : "=l"(r) : "f"(lo), "f"(hi)); return r;
}
__device__ __forceinline__ float2 upk(u64 v) {
    float2 f; asm("mov.b64 {%0,%1},%2;" : "=f"(f.x), "=f"(f.y) : "l"(v)); return f;
}
__device__ __forceinline__ u64 fma2_(u64 a, u64 b, u64 c) {
    u64 d; asm("fma.rn.f32x2 %0,%1,%2,%3;" : "=l"(d) : "l"(a), "l"(b), "l"(c)); return d;
}
__device__ __forceinline__ u64 add2_(u64 a, u64 b) {
    u64 d; asm("add.rn.f32x2 %0,%1,%2;" : "=l"(d) : "l"(a), "l"(b)); return d;
}

// Scratch (device globals — no allocation allowed)
__device__ float g_Fpart[BB * CCH * NCHUNK * 72];   // [bc][chunk][u*6+k][re,im]
__device__ float4 g_d4[BB * CCH * HH * 3];          // [bc][h][12 floats]: |z|^2 autocorr coeffs

// ---------------------------------------------------------------------------
// Kernel 1 (identical to R9/R11, measured 27.3-27.5us): partial F[u][k] over
// a 64-row tile. Real-input symmetry: 7 accumulators, 3 complex twiddles/row.
// Thread = float4 of w. Block 128, grid (8, 96) = 768 blocks.
// ---------------------------------------------------------------------------
__global__ __launch_bounds__(128) void k1_coldft(const float* __restrict__ x) {
    const int chunk = blockIdx.x;
    const int bc    = blockIdx.y;
    const int t     = threadIdx.x;
    const int h0    = chunk * CROWS;

    __shared__ __align__(16) u64 twc[CROWS][3], tws[CROWS][3];
    __shared__ float sm_part[4][72];

    for (int i = t; i < CROWS * 3; i += 128) {
        int hl = i / 3, K = (i % 3) + 1;
        float a = TWO_PI * (float)(h0 + hl) * (1.0f / (float)HH) * (float)K;
        float s, c; __sincosf(a, &s, &c);
        twc[hl][K - 1] = pk(c, c);
        tws[hl][K - 1] = pk(s, s);
    }
    __syncthreads();

    u64 S0[2] = {0ULL, 0ULL};
    u64 Cr[3][2], Ci[3][2];
#pragma unroll
    for (int K = 0; K < 3; K++) { Cr[K][0] = Cr[K][1] = 0ULL; Ci[K][0] = Ci[K][1] = 0ULL; }

    const float4* xp = (const float4*)(x + (size_t)bc * HH * WW + (size_t)h0 * WW) + t;
#pragma unroll 8
    for (int hl = 0; hl < CROWS; ++hl) {
        float4 v = __ldg(xp + (size_t)hl * (WW / 4));
        u64 v01 = pk(v.x, v.y), v23 = pk(v.z, v.w);
        S0[0] = add2_(S0[0], v01);
        S0[1] = add2_(S0[1], v23);
#pragma unroll
        for (int K = 0; K < 3; K++) {
            u64 cc = twc[hl][K], ss = tws[hl][K];
            Cr[K][0] = fma2_(v01, cc, Cr[K][0]);
            Ci[K][0] = fma2_(v01, ss, Ci[K][0]);
            Cr[K][1] = fma2_(v23, cc, Cr[K][1]);
            Ci[K][1] = fma2_(v23, ss, Ci[K][1]);
        }
    }

    float cre[6][4], cim[6][4];
    {
        float2 a0 = upk(S0[0]), a1 = upk(S0[1]);
        cre[3][0] = a0.x; cre[3][1] = a0.y; cre[3][2] = a1.x; cre[3][3] = a1.y;
        cim[3][0] = cim[3][1] = cim[3][2] = cim[3][3] = 0.f;
#pragma unroll
        for (int K = 1; K <= 3; K++) {
            float2 r0 = upk(Cr[K - 1][0]), r1 = upk(Cr[K - 1][1]);
            float2 i0 = upk(Ci[K - 1][0]), i1 = upk(Ci[K - 1][1]);
            float rv[4] = { r0.x, r0.y, r1.x, r1.y };
            float iv[4] = { i0.x, i0.y, i1.x, i1.y };
            int um = 3 - K, up = 3 + K;
#pragma unroll
            for (int j = 0; j < 4; j++) {
                cre[um][j] = rv[j]; cim[um][j] = iv[j];
                if (up < 6) { cre[up][j] = rv[j]; cim[up][j] = -iv[j]; }
            }
        }
    }

    float Ec[4][6], Es[4][6];
#pragma unroll
    for (int j = 0; j < 4; j++) {
        float phi = TWO_PI * (float)(4 * t + j) * (1.0f / (float)WW);
        float c1, s1; __sincosf(phi, &s1, &c1);
        float c2 = c1 * c1 - s1 * s1, s2 = 2.f * c1 * s1;
        float c3 = c2 * c1 - s2 * s1, s3 = c2 * s1 + s2 * c1;
        Ec[j][0] = c3; Es[j][0] = s3;
        Ec[j][1] = c2; Es[j][1] = s2;
        Ec[j][2] = c1; Es[j][2] = s1;
        Ec[j][3] = 1.f; Es[j][3] = 0.f;
        Ec[j][4] = c1; Es[j][4] = -s1;
        Ec[j][5] = c2; Es[j][5] = -s2;
    }

    const int wid = t >> 5, lid = t & 31;
#pragma unroll
    for (int u = 0; u < 6; u++) {
        float fr[6], fi[6];
#pragma unroll
        for (int k = 0; k < 6; k++) { fr[k] = 0.f; fi[k] = 0.f; }
#pragma unroll
        for (int j = 0; j < 4; j++) {
            float gr = cre[u][j], gi = cim[u][j];
#pragma unroll
            for (int k = 0; k < 6; k++) {
                fr[k] = fmaf(gr, Ec[j][k], fmaf(-gi, Es[j][k], fr[k]));
                fi[k] = fmaf(gr, Es[j][k], fmaf( gi, Ec[j][k], fi[k]));
            }
        }
#pragma unroll
        for (int off = 16; off >= 1; off >>= 1) {
#pragma unroll
            for (int k = 0; k < 6; k++) {
                fr[k] += __shfl_xor_sync(0xFFFFFFFFu, fr[k], off);
                fi[k] += __shfl_xor_sync(0xFFFFFFFFu, fi[k], off);
            }
        }
        if (lid == 0) {
#pragma unroll
            for (int k = 0; k < 6; k++) {
                sm_part[wid][(u * 6 + k) * 2 + 0] = fr[k];
                sm_part[wid][(u * 6 + k) * 2 + 1] = fi[k];
            }
        }
    }
    __syncthreads();

    if (t < 72) {
        float s = sm_part[0][t] + sm_part[1][t] + sm_part[2][t] + sm_part[3][t];
        g_Fpart[((size_t)bc * NCHUNK + chunk) * 72 + t] = s;
    }
}

// ---------------------------------------------------------------------------
// Kernel 2: sum chunk partials -> F; gg[h][k] = sum_u F[u][k] D_u(h); then
// AUTOCORRELATION: |z|^2 = c0 + sum_m (2Re(c_m) cos m phi - 2Im(c_m) sin m phi),
// c_m = sum_k gg_k conj(gg_{k-m}). Stores 12 floats per (bc,h):
//   d[0]=c0, d[2m-1]=2Re(c_m), d[2m]=-2Im(c_m), d[11]=0.
// grid 96, block 512.
// ---------------------------------------------------------------------------
__global__ __launch_bounds__(512) void k2_reduce() {
    const int bc = blockIdx.x;
    const int t  = threadIdx.x;

    __shared__ float F[72];

    if (t < 72) {
        const float* fp = g_Fpart + (size_t)bc * NCHUNK * 72 + t;
        float s = 0.f;
#pragma unroll
        for (int c = 0; c < NCHUNK; c++) s += fp[c * 72];
        F[t] = s * (1.0f / ((float)HH * (float)WW));
    }
    __syncthreads();

    {
        float psi = TWO_PI * (float)t * (1.0f / (float)HH);
        float d1c, d1s; __sincosf(psi, &d1s, &d1c);
        float d2c = d1c * d1c - d1s * d1s, d2s = 2.f * d1c * d1s;
        float d3c = d2c * d1c - d2s * d1s, d3s = d2c * d1s + d2s * d1c;
        float Dc[6] = { d3c,  d2c,  d1c,  1.f, d1c, d2c };
        float Ds[6] = { -d3s, -d2s, -d1s, 0.f, d1s, d2s };

        float gr[6], gi[6];
#pragma unroll
        for (int k = 0; k < 6; k++) {
            float r = 0.f, im = 0.f;
#pragma unroll
            for (int u = 0; u < 6; u++) {
                float Fr = F[(u * 6 + k) * 2 + 0];
                float Fi = F[(u * 6 + k) * 2 + 1];
                r  += Fr * Dc[u] - Fi * Ds[u];
                im += Fr * Ds[u] + Fi * Dc[u];
            }
            gr[k] = r; gi[k] = im;
        }

        // autocorrelation coefficients
        float d[12];
        {
            float c0 = 0.f;
#pragma unroll
            for (int k = 0; k < 6; k++) c0 = fmaf(gr[k], gr[k], fmaf(gi[k], gi[k], c0));
            d[0] = c0;
#pragma unroll
            for (int m = 1; m <= 5; m++) {
                float re = 0.f, im = 0.f;
#pragma unroll
                for (int k = m; k < 6; k++) {
                    re = fmaf(gr[k], gr[k - m], fmaf(gi[k], gi[k - m], re));
                    im = fmaf(gi[k], gr[k - m], fmaf(-gr[k], gi[k - m], im));
                }
                d[2 * m - 1] = 2.f * re;
                d[2 * m]     = -2.f * im;
            }
            d[11] = 0.f;
        }

        float4* dp = g_d4 + ((size_t)bc * HH + t) * 3;
        dp[0] = make_float4(d[0], d[1], d[2],  d[3]);
        dp[1] = make_float4(d[4], d[5], d[6],  d[7]);
        dp[2] = make_float4(d[8], d[9], d[10], d[11]);
    }
}

// ---------------------------------------------------------------------------
// Kernel 3: |z| via autocorr (10 scalar FMA per channel per pixel, no zi),
// then MLP + residual + clip. Plain scalar FFMA throughout.
// Thread = 2 adjacent pixels. grid (H/8, B) = (64, 32), block 256.
// ---------------------------------------------------------------------------
__global__ __launch_bounds__(256) void k3_final(const float* __restrict__ w1,
                                                const float* __restrict__ b1,
                                                const float* __restrict__ w2,
                                                const float* __restrict__ b2,
                                                float* __restrict__ out) {
    const int b  = blockIdx.y;
    const int h0 = blockIdx.x * R3ROWS;
    const int t  = threadIdx.x;   // pixel pair (2t, 2t+1)

    __shared__ __align__(16) float sd[R3ROWS * 3 * 12];  // [r][ch][12]
    __shared__ float wt[64];

    if (t < 72) {   // 72 float4 = 288 floats
        int r  = t / 9;
        int ch = (t % 9) / 3;
        int q  = t % 3;
        ((float4*)sd)[t] = g_d4[(((size_t)(b * 3 + ch) * HH) + (h0 + r)) * 3 + q];
    } else if (t >= 128 && t < 128 + 24) {
        wt[t - 128] = w1[t - 128];
    } else if (t >= 128 + 24 && t < 128 + 32) {
        wt[t - 128] = b1[t - 152];
    } else if (t >= 128 + 32 && t < 128 + 56) {
        wt[t - 128] = w2[t - 160];
    } else if (t >= 128 + 56 && t < 128 + 59) {
        wt[t - 128] = b2[t - 184];
    }
    __syncthreads();

    float W1r[8][3], B1r[8], W2r[3][8], B2r[3];
#pragma unroll
    for (int j = 0; j < 8; j++) {
#pragma unroll
        for (int cc = 0; cc < 3; cc++) W1r[j][cc] = wt[j * 3 + cc];
        B1r[j] = wt[24 + j];
    }
#pragma unroll
    for (int cc = 0; cc < 3; cc++) {
#pragma unroll
        for (int j = 0; j < 8; j++) W2r[cc][j] = wt[32 + cc * 8 + j];
        B2r[cc] = wt[56 + cc];
    }

    // cos/sin basis for m=1..5, both pixels (Chebyshev recurrence, hoisted)
    float cA[6], sA[6], cB[6], sB[6];
    {
        const int w0 = 2 * t;
        __sincosf(TWO_PI * (float)w0       * (1.0f / (float)WW), &sA[1], &cA[1]);
        __sincosf(TWO_PI * (float)(w0 + 1) * (1.0f / (float)WW), &sB[1], &cB[1]);
        float kA = 2.f * cA[1], kB = 2.f * cB[1];
        cA[0] = 1.f; sA[0] = 0.f; cB[0] = 1.f; sB[0] = 0.f;
#pragma unroll
        for (int m = 2; m <= 5; m++) {
            cA[m] = fmaf(kA, cA[m - 1], -cA[m - 2]);
            sA[m] = fmaf(kA, sA[m - 1], -sA[m - 2]);
            cB[m] = fmaf(kB, cB[m - 1], -cB[m - 2]);
            sB[m] = fmaf(kB, sB[m - 1], -sB[m - 2]);
        }
    }

#pragma unroll
    for (int r = 0; r < R3ROWS; ++r) {
        float lpA[3], lpB[3];
#pragma unroll
        for (int ch = 0; ch < 3; ch++) {
            const float* dd = &sd[(r * 3 + ch) * 12];
            float sa = dd[0], sb = dd[0];
#pragma unroll
            for (int m = 1; m <= 5; m++) {
                float dre = dd[2 * m - 1], dim = dd[2 * m];
                sa = fmaf(dre, cA[m], fmaf(dim, sA[m], sa));
                sb = fmaf(dre, cB[m], fmaf(dim, sB[m], sb));
            }
            sa = fmaxf(sa, 0.f);
            sb = fmaxf(sb, 0.f);
            lpA[ch] = sa * __frsqrt_rn(fmaxf(sa, 1e-30f));
            lpB[ch] = sb * __frsqrt_rn(fmaxf(sb, 1e-30f));
        }

        float hA[8], hB[8];
#pragma unroll
        for (int j = 0; j < 8; j++) {
            float aA = B1r[j], aB = B1r[j];
            aA = fmaf(W1r[j][0], lpA[0], aA);  aB = fmaf(W1r[j][0], lpB[0], aB);
            aA = fmaf(W1r[j][1], lpA[1], aA);  aB = fmaf(W1r[j][1], lpB[1], aB);
            aA = fmaf(W1r[j][2], lpA[2], aA);  aB = fmaf(W1r[j][2], lpB[2], aB);
            hA[j] = fmaxf(aA, 0.f);            hB[j] = fmaxf(aB, 0.f);
        }

#pragma unroll
        for (int ch = 0; ch < 3; ch++) {
            float yA = B2r[ch] + lpA[ch];
            float yB = B2r[ch] + lpB[ch];
#pragma unroll
            for (int j = 0; j < 8; j++) {
                yA = fmaf(W2r[ch][j], hA[j], yA);
                yB = fmaf(W2r[ch][j], hB[j], yB);
            }
            float2 yv;
            yv.x = __saturatef(yA);
            yv.y = __saturatef(yB);
            float2* orow = (float2*)(out + (((size_t)(b * 3 + ch) * HH) + (h0 + r)) * WW);
            orow[t] = yv;
        }
    }
}

// ---------------------------------------------------------------------------
extern "C" void kernel_launch(void* const* d_in, const int* in_sizes, int n_in,
                              void* d_out, int out_size) {
    const float* x  = (const float*)d_in[0];
    const float* w1 = (const float*)d_in[1];
    const float* b1 = (const float*)d_in[2];
    const float* w2 = (const float*)d_in[3];
    const float* b2 = (const float*)d_in[4];
    float* out = (float*)d_out;

    k1_coldft<<<dim3(NCHUNK, BB * CCH), 128>>>(x);
    k2_reduce<<<BB * CCH, 512>>>();
    k3_final<<<dim3(HH / R3ROWS, BB), 256>>>(w1, b1, w2, b2, out);
}